// round 9
// baseline (speedup 1.0000x reference)
#include <cuda_runtime.h>
#include <math.h>
#include <stdint.h>

#define Bb   2
#define Ll   1024
#define Dd   256
#define Kk   64
#define K2   128          // 2K (re|im concat)
#define NTOK (Bb*Ll)      // 2048
#define CH   128          // scan chunk length
#define NC   (Ll/CH)      // 8
#define NCH  (Bb*NC)      // 16
#define EPSv 1e-5f
#define PIv  3.14159265358979323846f

// ------------------------- scratch (static device memory) -------------------
__device__ float g_hk  [NTOK*Dd];
__device__ float g_hq  [NTOK*Dd];
__device__ float g_kk  [NTOK*K2];
__device__ float g_qq  [NTOK*K2];
__device__ float g_V   [NTOK*Dd];
__device__ float g_G   [NCH*K2*Dd];
__device__ float g_S   [NCH*K2*Dd];
__device__ float g_A   [NCH*CH*CH];
__device__ float g_ret [NTOK*Dd];
__device__ float g_rn  [NTOK*Dd];

// ------------------------- tf32 mma primitives ------------------------------
__device__ __forceinline__ float to_tf32(float x) {
    uint32_t u;
    asm("cvt.rna.tf32.f32 %0, %1;" : "=r"(u) : "f"(x));
    return __uint_as_float(u);
}

__device__ __forceinline__ void mma8(float c[4], const uint32_t a[4], const uint32_t b[2]) {
    asm volatile(
        "mma.sync.aligned.m16n8k8.row.col.f32.tf32.tf32.f32 "
        "{%0,%1,%2,%3}, {%4,%5,%6,%7}, {%8,%9}, {%0,%1,%2,%3};"
        : "+f"(c[0]), "+f"(c[1]), "+f"(c[2]), "+f"(c[3])
        : "r"(a[0]), "r"(a[1]), "r"(a[2]), "r"(a[3]), "r"(b[0]), "r"(b[1]));
}

// ---- tile loaders: dst is [16][68] holding [k][m-or-n], values tf32-rounded.
// direct: src[k][q] with q contiguous (ld = row stride), origin = col offset
__device__ __forceinline__ void load_direct(float (*dst)[68], const float* __restrict__ src,
                                            int ld, int origin, int k0, int tid)
{
    #pragma unroll
    for (int i = 0; i < 2; i++) {
        int idx = tid + i * 128;           // 0..255
        int k  = idx >> 4;                 // 0..15
        int q  = (idx & 15) * 4;           // 0..60
        float4 v = *(const float4*)&src[(long)(k0 + k) * ld + origin + q];
        dst[k][q + 0] = to_tf32(v.x);
        dst[k][q + 1] = to_tf32(v.y);
        dst[k][q + 2] = to_tf32(v.z);
        dst[k][q + 3] = to_tf32(v.w);
    }
}

// scatter: src[r][k] with k contiguous (ld = row stride), 64 rows starting at origin
__device__ __forceinline__ void load_scatter(float (*dst)[68], const float* __restrict__ src,
                                             int ld, int origin, int k0, int tid)
{
    int m  = tid >> 1;                     // 0..63
    int kq = (tid & 1) * 8;                // 0 or 8
    float4 v1 = *(const float4*)&src[(long)(origin + m) * ld + k0 + kq];
    float4 v2 = *(const float4*)&src[(long)(origin + m) * ld + k0 + kq + 4];
    dst[kq + 0][m] = to_tf32(v1.x); dst[kq + 1][m] = to_tf32(v1.y);
    dst[kq + 2][m] = to_tf32(v1.z); dst[kq + 3][m] = to_tf32(v1.w);
    dst[kq + 4][m] = to_tf32(v2.x); dst[kq + 5][m] = to_tf32(v2.y);
    dst[kq + 6][m] = to_tf32(v2.z); dst[kq + 7][m] = to_tf32(v2.w);
}

// one k-slice of warp-tile mma: warp computes 32x32 (2 mtiles x 4 ntiles)
__device__ __forceinline__ void mma_slice(const float (*As)[68], const float (*Bs)[68],
                                          int wm, int wn, int g, int t, float c[2][4][4])
{
    #pragma unroll
    for (int ks = 0; ks < 16; ks += 8) {
        uint32_t a[2][4], b[4][2];
        #pragma unroll
        for (int mt = 0; mt < 2; mt++) {
            a[mt][0] = __float_as_uint(As[ks + t    ][wm + mt * 16 + g    ]);
            a[mt][1] = __float_as_uint(As[ks + t    ][wm + mt * 16 + g + 8]);
            a[mt][2] = __float_as_uint(As[ks + t + 4][wm + mt * 16 + g    ]);
            a[mt][3] = __float_as_uint(As[ks + t + 4][wm + mt * 16 + g + 8]);
        }
        #pragma unroll
        for (int nt = 0; nt < 4; nt++) {
            b[nt][0] = __float_as_uint(Bs[ks + t    ][wn + nt * 8 + g]);
            b[nt][1] = __float_as_uint(Bs[ks + t + 4][wn + nt * 8 + g]);
        }
        #pragma unroll
        for (int mt = 0; mt < 2; mt++)
            #pragma unroll
            for (int nt = 0; nt < 4; nt++)
                mma8(c[mt][nt], a[mt], b[nt]);
    }
}

// ------------------------- generic tf32 GEMM ---------------------------------
// 64x64 tile, 128 threads (4 warps, 32x32 warp tiles). gridDim.z = batch.
enum { M_PLAIN = 0, M_MASK = 4, M_RESID = 5 };

template<int MODE, bool TA, bool TB>
__global__ void tgemm_kernel(const float* __restrict__ A, const float* __restrict__ Bm,
                             const float* __restrict__ bias, const float* __restrict__ extra,
                             float* __restrict__ C,
                             int M, int N, int Kd,
                             long sA, long sB, long sC)
{
    A  += (long)blockIdx.z * sA;
    Bm += (long)blockIdx.z * sB;
    C  += (long)blockIdx.z * sC;
    if (MODE == M_RESID && extra) extra += (long)blockIdx.z * sC;

    __shared__ __align__(16) float As[16][68];
    __shared__ __align__(16) float Bs[16][68];

    const int tid  = threadIdx.x;
    const int lane = tid & 31, wid = tid >> 5;
    const int wm = (wid >> 1) * 32, wn = (wid & 1) * 32;
    const int g = lane >> 2, t = lane & 3;
    const int rowTile = blockIdx.y * 64;
    const int colTile = blockIdx.x * 64;

    float c[2][4][4] = {};

    for (int k0 = 0; k0 < Kd; k0 += 16) {
        if (!TA) load_scatter(As, A, Kd, rowTile, k0, tid);   // A[m][k]
        else     load_direct (As, A, M,  rowTile, k0, tid);   // A[k][m]
        if (!TB) load_direct (Bs, Bm, N,  colTile, k0, tid);  // B[k][n]
        else     load_scatter(Bs, Bm, Kd, colTile, k0, tid);  // B[n][k]
        __syncthreads();
        mma_slice(As, Bs, wm, wn, g, t, c);
        __syncthreads();
    }

    #pragma unroll
    for (int mt = 0; mt < 2; mt++)
        #pragma unroll
        for (int nt = 0; nt < 4; nt++) {
            int col = colTile + wn + nt * 8 + 2 * t;
            #pragma unroll
            for (int dr = 0; dr < 2; dr++) {
                int r = rowTile + wm + mt * 16 + g + dr * 8;
                float v0 = c[mt][nt][dr * 2 + 0];
                float v1 = c[mt][nt][dr * 2 + 1];
                if (MODE == M_RESID) {
                    v0 += bias[col]     + extra[(long)r * N + col];
                    v1 += bias[col + 1] + extra[(long)r * N + col + 1];
                }
                if (MODE == M_MASK) {
                    if (col     > r) v0 = 0.0f;
                    if (col + 1 > r) v1 = 0.0f;
                }
                *(float2*)&C[(long)r * N + col] = make_float2(v0, v1);
            }
        }
}

// ------------------------- encoder pre-GEMM (z=3, tf32) ----------------------
__global__ void enc_gemm_kernel(const float* __restrict__ x,
                                const float* __restrict__ pos_k, const float* __restrict__ pos_q,
                                const float* __restrict__ w1_k, const float* __restrict__ b1_k,
                                const float* __restrict__ w1_q, const float* __restrict__ b1_q,
                                const float* __restrict__ wv,   const float* __restrict__ bv,
                                float* __restrict__ hk, float* __restrict__ hq, float* __restrict__ V)
{
    const int z = blockIdx.z;
    const float* W;  const float* bias; const float* pos; float* C;
    if (z == 0)      { W = w1_k; bias = b1_k; pos = pos_k; C = hk; }
    else if (z == 1) { W = w1_q; bias = b1_q; pos = pos_q; C = hq; }
    else             { W = wv;   bias = bv;   pos = nullptr; C = V; }

    __shared__ __align__(16) float As[16][68];
    __shared__ __align__(16) float Bs[16][68];

    const int tid  = threadIdx.x;
    const int lane = tid & 31, wid = tid >> 5;
    const int wm = (wid >> 1) * 32, wn = (wid & 1) * 32;
    const int g = lane >> 2, t = lane & 3;
    const int rowTile = blockIdx.y * 64;
    const int colTile = blockIdx.x * 64;

    float c[2][4][4] = {};

    for (int k0 = 0; k0 < Dd; k0 += 16) {
        {   // A = x (+pos), scatter transpose
            int m  = tid >> 1;
            int kq = (tid & 1) * 8;
            int row = rowTile + m;
            float4 v1 = *(const float4*)&x[(long)row * Dd + k0 + kq];
            float4 v2 = *(const float4*)&x[(long)row * Dd + k0 + kq + 4];
            if (pos) {
                const float* pr = &pos[(long)(row & (Ll - 1)) * Dd + k0 + kq];
                float4 p1 = *(const float4*)pr;
                float4 p2 = *(const float4*)(pr + 4);
                v1.x += p1.x; v1.y += p1.y; v1.z += p1.z; v1.w += p1.w;
                v2.x += p2.x; v2.y += p2.y; v2.z += p2.z; v2.w += p2.w;
            }
            As[kq + 0][m] = to_tf32(v1.x); As[kq + 1][m] = to_tf32(v1.y);
            As[kq + 2][m] = to_tf32(v1.z); As[kq + 3][m] = to_tf32(v1.w);
            As[kq + 4][m] = to_tf32(v2.x); As[kq + 5][m] = to_tf32(v2.y);
            As[kq + 6][m] = to_tf32(v2.z); As[kq + 7][m] = to_tf32(v2.w);
        }
        load_direct(Bs, W, Dd, colTile, k0, tid);
        __syncthreads();
        mma_slice(As, Bs, wm, wn, g, t, c);
        __syncthreads();
    }

    #pragma unroll
    for (int mt = 0; mt < 2; mt++)
        #pragma unroll
        for (int nt = 0; nt < 4; nt++) {
            int col = colTile + wn + nt * 8 + 2 * t;
            #pragma unroll
            for (int dr = 0; dr < 2; dr++) {
                int r = rowTile + wm + mt * 16 + g + dr * 8;
                float v0 = c[mt][nt][dr * 2 + 0] + bias[col];
                float v1 = c[mt][nt][dr * 2 + 1] + bias[col + 1];
                if (z < 2) {
                    v0 = 0.5f * v0 * (1.0f + erff(v0 * 0.70710678118654752440f));
                    v1 = 0.5f * v1 * (1.0f + erff(v1 * 0.70710678118654752440f));
                }
                *(float2*)&C[(long)r * Dd + col] = make_float2(v0, v1);
            }
        }
}

// ------------------------- fused head GEMMs + phasor (z=2, tf32) -------------
// Tile: 64 tokens x 64 features. Dual mma: phase = h@w2, amp = (x+pos)@wa.
__global__ void phasor_gemm_kernel(const float* __restrict__ x,
                                   const float* __restrict__ pos_k, const float* __restrict__ pos_q,
                                   const float* __restrict__ hk,   const float* __restrict__ hq,
                                   const float* __restrict__ w2_k, const float* __restrict__ b2_k,
                                   const float* __restrict__ wa_k, const float* __restrict__ ba_k,
                                   const float* __restrict__ w2_q, const float* __restrict__ b2_q,
                                   const float* __restrict__ wa_q, const float* __restrict__ ba_q,
                                   float* __restrict__ kk, float* __restrict__ qq)
{
    const int z = blockIdx.z;
    const float* h   = z ? hq    : hk;
    const float* pos = z ? pos_q : pos_k;
    const float* W2  = z ? w2_q  : w2_k;
    const float* B2  = z ? b2_q  : b2_k;
    const float* Wa  = z ? wa_q  : wa_k;
    const float* Ba  = z ? ba_q  : ba_k;
    float* out       = z ? qq    : kk;

    __shared__ __align__(16) float Ah[16][68];
    __shared__ __align__(16) float Ax[16][68];
    __shared__ __align__(16) float Bp[16][68];
    __shared__ __align__(16) float Bam[16][68];

    const int tid  = threadIdx.x;
    const int lane = tid & 31, wid = tid >> 5;
    const int wm = (wid >> 1) * 32, wn = (wid & 1) * 32;
    const int g = lane >> 2, t = lane & 3;
    const int rowTile = blockIdx.y * 64;

    float cP[2][4][4] = {};
    float cA[2][4][4] = {};

    for (int k0 = 0; k0 < Dd; k0 += 16) {
        load_scatter(Ah, h, Dd, rowTile, k0, tid);
        {   // x + pos scatter
            int m  = tid >> 1;
            int kq = (tid & 1) * 8;
            int row = rowTile + m;
            float4 v1 = *(const float4*)&x[(long)row * Dd + k0 + kq];
            float4 v2 = *(const float4*)&x[(long)row * Dd + k0 + kq + 4];
            const float* pr = &pos[(long)(row & (Ll - 1)) * Dd + k0 + kq];
            float4 p1 = *(const float4*)pr;
            float4 p2 = *(const float4*)(pr + 4);
            Ax[kq + 0][m] = to_tf32(v1.x + p1.x); Ax[kq + 1][m] = to_tf32(v1.y + p1.y);
            Ax[kq + 2][m] = to_tf32(v1.z + p1.z); Ax[kq + 3][m] = to_tf32(v1.w + p1.w);
            Ax[kq + 4][m] = to_tf32(v2.x + p2.x); Ax[kq + 5][m] = to_tf32(v2.y + p2.y);
            Ax[kq + 6][m] = to_tf32(v2.z + p2.z); Ax[kq + 7][m] = to_tf32(v2.w + p2.w);
        }
        load_direct(Bp,  W2, Kk, 0, k0, tid);
        load_direct(Bam, Wa, Kk, 0, k0, tid);
        __syncthreads();
        mma_slice(Ah, Bp,  wm, wn, g, t, cP);
        mma_slice(Ax, Bam, wm, wn, g, t, cA);
        __syncthreads();
    }

    #pragma unroll
    for (int mt = 0; mt < 2; mt++)
        #pragma unroll
        for (int nt = 0; nt < 4; nt++) {
            int col = wn + nt * 8 + 2 * t;       // feature 0..63
            #pragma unroll
            for (int dr = 0; dr < 2; dr++) {
                int n = rowTile + wm + mt * 16 + g + dr * 8;  // token
                #pragma unroll
                for (int dc = 0; dc < 2; dc++) {
                    int cc = col + dc;
                    float p = cP[mt][nt][dr * 2 + dc] + B2[cc];
                    float a = cA[mt][nt][dr * 2 + dc] + Ba[cc];
                    float ph = tanhf(p) * PIv;
                    float sp = fmaxf(a, 0.0f) + log1pf(expf(-fabsf(a)));
                    float amp = sp + 0.1f;
                    float s, cs;
                    sincosf(ph, &s, &cs);
                    out[(long)n * K2 + cc]      = amp * cs;
                    out[(long)n * K2 + Kk + cc] = amp * s;
                }
            }
        }
}

// ------------------------- fused retrieval GEMM: ret = A@V + QQ@S (tf32) -----
__global__ void ret_gemm_kernel(const float* __restrict__ Amat, const float* __restrict__ V,
                                const float* __restrict__ QQ,   const float* __restrict__ S,
                                float* __restrict__ ret)
{
    const int z = blockIdx.z;  // chunk
    const float* Ab = Amat + (long)z * CH * CH;
    const float* Vb = V    + (long)z * CH * Dd;
    const float* Qb = QQ   + (long)z * CH * K2;
    const float* Sb = S    + (long)z * K2 * Dd;
    float*       Cb = ret  + (long)z * CH * Dd;

    __shared__ __align__(16) float As[16][68];
    __shared__ __align__(16) float Bs[16][68];

    const int tid  = threadIdx.x;
    const int lane = tid & 31, wid = tid >> 5;
    const int wm = (wid >> 1) * 32, wn = (wid & 1) * 32;
    const int g = lane >> 2, t = lane & 3;
    const int rowTile = blockIdx.y * 64;
    const int colTile = blockIdx.x * 64;

    float c[2][4][4] = {};

    #pragma unroll 1
    for (int phase = 0; phase < 2; phase++) {
        const float* Ap = phase ? Qb : Ab;     // both lda = 128
        const float* Bp = phase ? Sb : Vb;     // both ldb = 256
        for (int k0 = 0; k0 < 128; k0 += 16) {
            load_scatter(As, Ap, 128, rowTile, k0, tid);
            load_direct (Bs, Bp, Dd,  colTile, k0, tid);
            __syncthreads();
            mma_slice(As, Bs, wm, wn, g, t, c);
            __syncthreads();
        }
    }

    #pragma unroll
    for (int mt = 0; mt < 2; mt++)
        #pragma unroll
        for (int nt = 0; nt < 4; nt++) {
            int col = colTile + wn + nt * 8 + 2 * t;
            #pragma unroll
            for (int dr = 0; dr < 2; dr++) {
                int r = rowTile + wm + mt * 16 + g + dr * 8;
                *(float2*)&Cb[(long)r * Dd + col] =
                    make_float2(c[mt][nt][dr * 2 + 0], c[mt][nt][dr * 2 + 1]);
            }
        }
}

// ------------------------- small kernels ------------------------------------
// exclusive prefix over the NC chunk states: S[b,c] = sum_{c'<c} G[b,c']
__global__ void prefix_kernel()
{
    const int KD4 = K2 * Dd / 4;   // 8192 float4 per chunk state
    int i = blockIdx.x * blockDim.x + threadIdx.x;
    if (i >= Bb * KD4) return;
    int b = i / KD4, r = i % KD4;
    const float4* G4 = reinterpret_cast<const float4*>(g_G);
    float4*       S4 = reinterpret_cast<float4*>(g_S);

    float4 g[NC];
    #pragma unroll
    for (int c = 0; c < NC; c++)
        g[c] = G4[(long)(b * NC + c) * KD4 + r];

    float4 acc = make_float4(0.f, 0.f, 0.f, 0.f);
    #pragma unroll
    for (int c = 0; c < NC; c++) {
        S4[(long)(b * NC + c) * KD4 + r] = acc;
        acc.x += g[c].x; acc.y += g[c].y;
        acc.z += g[c].z; acc.w += g[c].w;
    }
}

// normalize by sqrt((l+1)*K), layernorm
__global__ void ln_kernel(const float* __restrict__ ret,
                          const float* __restrict__ gg,
                          const float* __restrict__ bb,
                          float* __restrict__ rn)
{
    int n = blockIdx.x;
    int l = n % Ll;
    int d = threadIdx.x;      // 256 threads == D
    float v = ret[(long)n * Dd + d] * rsqrtf((float)(l + 1) * (float)Kk);

    float s = v, s2 = v * v;
    #pragma unroll
    for (int o = 16; o; o >>= 1) {
        s  += __shfl_xor_sync(0xffffffffu, s,  o);
        s2 += __shfl_xor_sync(0xffffffffu, s2, o);
    }
    __shared__ float ss[8], ss2[8];
    int w = d >> 5, lane = d & 31;
    if (lane == 0) { ss[w] = s; ss2[w] = s2; }
    __syncthreads();
    if (w == 0) {
        float a  = (lane < 8) ? ss[lane]  : 0.0f;
        float a2 = (lane < 8) ? ss2[lane] : 0.0f;
        #pragma unroll
        for (int o = 4; o; o >>= 1) {
            a  += __shfl_xor_sync(0xffffffffu, a,  o);
            a2 += __shfl_xor_sync(0xffffffffu, a2, o);
        }
        if (lane == 0) { ss[0] = a; ss2[0] = a2; }
    }
    __syncthreads();
    float mu  = ss[0] / Dd;
    float var = ss2[0] / Dd - mu * mu;
    rn[(long)n * Dd + d] = (v - mu) * rsqrtf(var + EPSv) * gg[d] + bb[d];
}

// ------------------------- host launcher ------------------------------------
extern "C" void kernel_launch(void* const* d_in, const int* in_sizes, int n_in,
                              void* d_out, int out_size)
{
    const float* x     = (const float*)d_in[0];
    const float* pos_k = (const float*)d_in[1];
    const float* w1_k  = (const float*)d_in[2];
    const float* b1_k  = (const float*)d_in[3];
    const float* w2_k  = (const float*)d_in[4];
    const float* b2_k  = (const float*)d_in[5];
    const float* wa_k  = (const float*)d_in[6];
    const float* ba_k  = (const float*)d_in[7];
    const float* pos_q = (const float*)d_in[8];
    const float* w1_q  = (const float*)d_in[9];
    const float* b1_q  = (const float*)d_in[10];
    const float* w2_q  = (const float*)d_in[11];
    const float* b2_q  = (const float*)d_in[12];
    const float* wa_q  = (const float*)d_in[13];
    const float* ba_q  = (const float*)d_in[14];
    const float* wv    = (const float*)d_in[15];
    const float* bv    = (const float*)d_in[16];
    const float* ln_g  = (const float*)d_in[17];
    const float* ln_b  = (const float*)d_in[18];
    const float* wo    = (const float*)d_in[19];
    const float* bo    = (const float*)d_in[20];
    float* out = (float*)d_out;

    float *hk, *hq, *kk, *qq, *V, *G, *S, *Amat, *ret, *rn;
    cudaGetSymbolAddress((void**)&hk,   g_hk);
    cudaGetSymbolAddress((void**)&hq,   g_hq);
    cudaGetSymbolAddress((void**)&kk,   g_kk);
    cudaGetSymbolAddress((void**)&qq,   g_qq);
    cudaGetSymbolAddress((void**)&V,    g_V);
    cudaGetSymbolAddress((void**)&G,    g_G);
    cudaGetSymbolAddress((void**)&S,    g_S);
    cudaGetSymbolAddress((void**)&Amat, g_A);
    cudaGetSymbolAddress((void**)&ret,  g_ret);
    cudaGetSymbolAddress((void**)&rn,   g_rn);

    // 1. hk = gelu((x+pos_k)@w1_k+b1), hq likewise, V = x@wv+bv  (z=3, tf32)
    enc_gemm_kernel<<<dim3(4, 32, 3), 128>>>(x, pos_k, pos_q,
                                             w1_k, b1_k, w1_q, b1_q, wv, bv,
                                             hk, hq, V);

    // 2. fused head GEMMs + phasor -> kk, qq  (z=2, tf32)
    phasor_gemm_kernel<<<dim3(1, 32, 2), 128>>>(x, pos_k, pos_q, hk, hq,
                                                w2_k, b2_k, wa_k, ba_k,
                                                w2_q, b2_q, wa_q, ba_q,
                                                kk, qq);

    // 3. per-chunk state: G[c] = KK_c^T @ V_c  (batched TN, 16 chunks, tf32)
    tgemm_kernel<M_PLAIN, true, false><<<dim3(4, 2, NCH), 128>>>(
        kk, V, nullptr, nullptr, G, K2, Dd, CH,
        (long)CH * K2, (long)CH * Dd, (long)K2 * Dd);

    // 4. exclusive prefix over chunks -> S
    prefix_kernel<<<(Bb * K2 * Dd / 4 + 63) / 64, 64>>>();

    // 5. intra-chunk attention matrix A = tril(QQ_c @ KK_c^T)  (tf32)
    tgemm_kernel<M_MASK, false, true><<<dim3(2, 2, NCH), 128>>>(
        qq, kk, nullptr, nullptr, Amat, CH, CH, K2,
        (long)CH * K2, (long)CH * K2, (long)CH * CH);

    // 6. ret_c = A_c @ V_c + QQ_c @ S_c  (fused dual GEMM, tf32)
    ret_gemm_kernel<<<dim3(4, 2, NCH), 128>>>(Amat, V, qq, S, ret);

    // 7. normalize + layernorm
    ln_kernel<<<NTOK, 256>>>(ret, ln_g, ln_b, rn);

    // 8. out = x + rn @ wo + bo  (tf32)
    tgemm_kernel<M_RESID, false, false><<<dim3(4, 32, 1), 128>>>(
        rn, wo, bo, x, out, NTOK, Dd, Dd, 0, 0, 0);
}

// round 10
// speedup vs baseline: 1.1471x; 1.1471x over previous
#include <cuda_runtime.h>
#include <math.h>
#include <stdint.h>

#define Bb   2
#define Ll   1024
#define Dd   256
#define Kk   64
#define K2   128          // 2K (re|im concat)
#define NTOK (Bb*Ll)      // 2048
#define CH   128          // scan chunk length
#define NC   (Ll/CH)      // 8
#define NCH  (Bb*NC)      // 16
#define EPSv 1e-5f
#define PIv  3.14159265358979323846f

// ------------------------- scratch (static device memory) -------------------
__device__ float g_hk  [NTOK*Dd];
__device__ float g_hq  [NTOK*Dd];
__device__ float g_kk  [NTOK*K2];
__device__ float g_qq  [NTOK*K2];
__device__ float g_V   [NTOK*Dd];
__device__ float g_G   [NCH*K2*Dd];
__device__ float g_S   [NCH*K2*Dd];
__device__ float g_A   [NCH*CH*CH];
__device__ float g_ret [NTOK*Dd];
__device__ float g_rn  [NTOK*Dd];

// ------------------------- tf32 mma primitives ------------------------------
__device__ __forceinline__ float to_tf32(float x) {
    uint32_t u;
    asm("cvt.rna.tf32.f32 %0, %1;" : "=r"(u) : "f"(x));
    return __uint_as_float(u);
}
__device__ __forceinline__ float4 tf32x4(float4 v) {
    return make_float4(to_tf32(v.x), to_tf32(v.y), to_tf32(v.z), to_tf32(v.w));
}

__device__ __forceinline__ void mma8(float c[4], const uint32_t a[4], const uint32_t b[2]) {
    asm volatile(
        "mma.sync.aligned.m16n8k8.row.col.f32.tf32.tf32.f32 "
        "{%0,%1,%2,%3}, {%4,%5,%6,%7}, {%8,%9}, {%0,%1,%2,%3};"
        : "+f"(c[0]), "+f"(c[1]), "+f"(c[2]), "+f"(c[3])
        : "r"(a[0]), "r"(a[1]), "r"(a[2]), "r"(a[3]), "r"(b[0]), "r"(b[1]));
}

// warp tile (16*MT) x 32 at (wm, wn). As flat [16][LDA] k-major, Bs [16][LDB].
template<int MT, int LDA, int LDB>
__device__ __forceinline__ void mma_frag(const float* As, const float* Bs,
                                         int wm, int wn, int g, int t,
                                         float (*c)[4][4])
{
    #pragma unroll
    for (int ks = 0; ks < 16; ks += 8) {
        uint32_t a[MT][4], b[4][2];
        #pragma unroll
        for (int mt = 0; mt < MT; mt++) {
            int m0 = wm + mt * 16 + g;
            a[mt][0] = __float_as_uint(As[(ks + t    ) * LDA + m0    ]);
            a[mt][1] = __float_as_uint(As[(ks + t    ) * LDA + m0 + 8]);
            a[mt][2] = __float_as_uint(As[(ks + t + 4) * LDA + m0    ]);
            a[mt][3] = __float_as_uint(As[(ks + t + 4) * LDA + m0 + 8]);
        }
        #pragma unroll
        for (int nt = 0; nt < 4; nt++) {
            int n0 = wn + nt * 8 + g;
            b[nt][0] = __float_as_uint(Bs[(ks + t    ) * LDB + n0]);
            b[nt][1] = __float_as_uint(Bs[(ks + t + 4) * LDB + n0]);
        }
        #pragma unroll
        for (int mt = 0; mt < MT; mt++)
            #pragma unroll
            for (int nt = 0; nt < 4; nt++)
                mma8(c[mt][nt], a[mt], b[nt]);
    }
}

// ---------------- prefetch register payloads + loaders (128x64 tile) --------
struct P8 { float4 u, v; };
struct P4 { float4 u; };

// A[m][k] (k contiguous), 128 rows. m=tid>>1, kq=(tid&1)*8
__device__ __forceinline__ void ldgA_mk(P8& p, const float* __restrict__ A,
                                        int ld, int rowTile, int k0, int tid) {
    int m = tid >> 1, kq = (tid & 1) * 8;
    const float* b = A + (long)(rowTile + m) * ld + k0 + kq;
    p.u = *(const float4*)b; p.v = *(const float4*)(b + 4);
}
__device__ __forceinline__ void stsA_mk(float* As, const P8& p, int tid) {
    int m = tid >> 1, kq = (tid & 1) * 8;
    As[(kq + 0) * 132 + m] = to_tf32(p.u.x); As[(kq + 1) * 132 + m] = to_tf32(p.u.y);
    As[(kq + 2) * 132 + m] = to_tf32(p.u.z); As[(kq + 3) * 132 + m] = to_tf32(p.u.w);
    As[(kq + 4) * 132 + m] = to_tf32(p.v.x); As[(kq + 5) * 132 + m] = to_tf32(p.v.y);
    As[(kq + 6) * 132 + m] = to_tf32(p.v.z); As[(kq + 7) * 132 + m] = to_tf32(p.v.w);
}
// A[k][m] (m contiguous, 128 wide). k=tid>>4, mq=(tid&15)*8
__device__ __forceinline__ void ldgA_km(P8& p, const float* __restrict__ A,
                                        int ld, int rowTile, int k0, int tid) {
    int k = tid >> 4, mq = (tid & 15) * 8;
    const float* b = A + (long)(k0 + k) * ld + rowTile + mq;
    p.u = *(const float4*)b; p.v = *(const float4*)(b + 4);
}
__device__ __forceinline__ void stsA_km(float* As, const P8& p, int tid) {
    int k = tid >> 4, mq = (tid & 15) * 8;
    *(float4*)&As[k * 132 + mq]     = tf32x4(p.u);
    *(float4*)&As[k * 132 + mq + 4] = tf32x4(p.v);
}
// B[k][n] (n contiguous). k=tid>>4, nq=(tid&15)*4
__device__ __forceinline__ void ldgB_kn(P4& p, const float* __restrict__ B,
                                        int ld, int colTile, int k0, int tid) {
    int k = tid >> 4, nq = (tid & 15) * 4;
    p.u = *(const float4*)&B[(long)(k0 + k) * ld + colTile + nq];
}
__device__ __forceinline__ void stsB_kn(float* Bs, const P4& p, int tid) {
    int k = tid >> 4, nq = (tid & 15) * 4;
    *(float4*)&Bs[k * 68 + nq] = tf32x4(p.u);
}
// B[n][k] (k contiguous). n=tid>>2, kq=(tid&3)*4
__device__ __forceinline__ void ldgB_nk(P4& p, const float* __restrict__ B,
                                        int ld, int colTile, int k0, int tid) {
    int n = tid >> 2, kq = (tid & 3) * 4;
    p.u = *(const float4*)&B[(long)(colTile + n) * ld + k0 + kq];
}
__device__ __forceinline__ void stsB_nk(float* Bs, const P4& p, int tid) {
    int n = tid >> 2, kq = (tid & 3) * 4;
    Bs[(kq + 0) * 68 + n] = to_tf32(p.u.x); Bs[(kq + 1) * 68 + n] = to_tf32(p.u.y);
    Bs[(kq + 2) * 68 + n] = to_tf32(p.u.z); Bs[(kq + 3) * 68 + n] = to_tf32(p.u.w);
}

// ------------------------- generic tf32 GEMM (128x64 tile) -------------------
// 256 threads = 8 warps of 32x32 (wm=(wid&3)*32, wn=(wid>>2)*32).
enum { M_PLAIN = 0, M_MASK = 4, M_RESID = 5 };

template<int MODE, bool TA, bool TB>
__global__ void tgemm_kernel(const float* __restrict__ A, const float* __restrict__ Bm,
                             const float* __restrict__ bias, const float* __restrict__ extra,
                             float* __restrict__ C,
                             int M, int N, int Kd,
                             long sA, long sB, long sC)
{
    A  += (long)blockIdx.z * sA;
    Bm += (long)blockIdx.z * sB;
    C  += (long)blockIdx.z * sC;
    if (MODE == M_RESID && extra) extra += (long)blockIdx.z * sC;

    __shared__ __align__(16) float As[2][16 * 132];
    __shared__ __align__(16) float Bs[2][16 * 68];

    const int tid  = threadIdx.x;
    const int lane = tid & 31, wid = tid >> 5;
    const int wm = (wid & 3) * 32, wn = (wid >> 2) * 32;
    const int g = lane >> 2, t = lane & 3;
    const int rowTile = blockIdx.y * 128;
    const int colTile = blockIdx.x * 64;

    float c[2][4][4] = {};
    P8 pa; P4 pb;

    // prologue: tile 0
    if (!TA) ldgA_mk(pa, A, Kd, rowTile, 0, tid);
    else     ldgA_km(pa, A, M,  rowTile, 0, tid);
    if (!TB) ldgB_kn(pb, Bm, N,  colTile, 0, tid);
    else     ldgB_nk(pb, Bm, Kd, colTile, 0, tid);
    if (!TA) stsA_mk(As[0], pa, tid); else stsA_km(As[0], pa, tid);
    if (!TB) stsB_kn(Bs[0], pb, tid); else stsB_nk(Bs[0], pb, tid);
    __syncthreads();

    const int T = Kd >> 4;
    for (int ti = 0; ti < T; ti++) {
        if (ti + 1 < T) {
            int k0 = (ti + 1) << 4;
            if (!TA) ldgA_mk(pa, A, Kd, rowTile, k0, tid);
            else     ldgA_km(pa, A, M,  rowTile, k0, tid);
            if (!TB) ldgB_kn(pb, Bm, N,  colTile, k0, tid);
            else     ldgB_nk(pb, Bm, Kd, colTile, k0, tid);
        }
        mma_frag<2, 132, 68>(As[ti & 1], Bs[ti & 1], wm, wn, g, t, c);
        if (ti + 1 < T) {
            int nb = (ti + 1) & 1;
            if (!TA) stsA_mk(As[nb], pa, tid); else stsA_km(As[nb], pa, tid);
            if (!TB) stsB_kn(Bs[nb], pb, tid); else stsB_nk(Bs[nb], pb, tid);
            __syncthreads();
        }
    }

    #pragma unroll
    for (int mt = 0; mt < 2; mt++)
        #pragma unroll
        for (int nt = 0; nt < 4; nt++) {
            int col = colTile + wn + nt * 8 + 2 * t;
            #pragma unroll
            for (int dr = 0; dr < 2; dr++) {
                int r = rowTile + wm + mt * 16 + g + dr * 8;
                float v0 = c[mt][nt][dr * 2 + 0];
                float v1 = c[mt][nt][dr * 2 + 1];
                if (MODE == M_RESID) {
                    v0 += bias[col]     + extra[(long)r * N + col];
                    v1 += bias[col + 1] + extra[(long)r * N + col + 1];
                }
                if (MODE == M_MASK) {
                    if (col     > r) v0 = 0.0f;
                    if (col + 1 > r) v1 = 0.0f;
                }
                *(float2*)&C[(long)r * N + col] = make_float2(v0, v1);
            }
        }
}

// ------------------------- encoder pre-GEMM (z=3, 128x64 tile) ---------------
__global__ void enc_gemm_kernel(const float* __restrict__ x,
                                const float* __restrict__ pos_k, const float* __restrict__ pos_q,
                                const float* __restrict__ w1_k, const float* __restrict__ b1_k,
                                const float* __restrict__ w1_q, const float* __restrict__ b1_q,
                                const float* __restrict__ wv,   const float* __restrict__ bv,
                                float* __restrict__ hk, float* __restrict__ hq, float* __restrict__ V)
{
    const int z = blockIdx.z;
    const float* W;  const float* bias; const float* pos; float* C;
    if (z == 0)      { W = w1_k; bias = b1_k; pos = pos_k; C = hk; }
    else if (z == 1) { W = w1_q; bias = b1_q; pos = pos_q; C = hq; }
    else             { W = wv;   bias = bv;   pos = nullptr; C = V; }

    __shared__ __align__(16) float As[2][16 * 132];
    __shared__ __align__(16) float Bs[2][16 * 68];

    const int tid  = threadIdx.x;
    const int lane = tid & 31, wid = tid >> 5;
    const int wm = (wid & 3) * 32, wn = (wid >> 2) * 32;
    const int g = lane >> 2, t = lane & 3;
    const int rowTile = blockIdx.y * 128;
    const int colTile = blockIdx.x * 64;

    float c[2][4][4] = {};
    P8 pa, pp; P4 pb;
    const int m = tid >> 1, kq = (tid & 1) * 8;
    const int posrow = (rowTile + m) & (Ll - 1);

    // prologue
    ldgA_mk(pa, x, Dd, rowTile, 0, tid);
    if (pos) ldgA_mk(pp, pos, Dd, posrow - m, 0, tid);  // rowTile surrogate so row = posrow
    else { pp.u = make_float4(0,0,0,0); pp.v = pp.u; }
    ldgB_kn(pb, W, Dd, colTile, 0, tid);
    {
        P8 s; s.u = make_float4(pa.u.x+pp.u.x, pa.u.y+pp.u.y, pa.u.z+pp.u.z, pa.u.w+pp.u.w);
        s.v = make_float4(pa.v.x+pp.v.x, pa.v.y+pp.v.y, pa.v.z+pp.v.z, pa.v.w+pp.v.w);
        stsA_mk(As[0], s, tid);
    }
    stsB_kn(Bs[0], pb, tid);
    __syncthreads();

    const int T = Dd >> 4;   // 16
    for (int ti = 0; ti < T; ti++) {
        if (ti + 1 < T) {
            int k0 = (ti + 1) << 4;
            ldgA_mk(pa, x, Dd, rowTile, k0, tid);
            if (pos) ldgA_mk(pp, pos, Dd, posrow - m, k0, tid);
            ldgB_kn(pb, W, Dd, colTile, k0, tid);
        }
        mma_frag<2, 132, 68>(As[ti & 1], Bs[ti & 1], wm, wn, g, t, c);
        if (ti + 1 < T) {
            int nb = (ti + 1) & 1;
            P8 s; s.u = make_float4(pa.u.x+pp.u.x, pa.u.y+pp.u.y, pa.u.z+pp.u.z, pa.u.w+pp.u.w);
            s.v = make_float4(pa.v.x+pp.v.x, pa.v.y+pp.v.y, pa.v.z+pp.v.z, pa.v.w+pp.v.w);
            stsA_mk(As[nb], s, tid);
            stsB_kn(Bs[nb], pb, tid);
            __syncthreads();
        }
    }

    #pragma unroll
    for (int mt = 0; mt < 2; mt++)
        #pragma unroll
        for (int nt = 0; nt < 4; nt++) {
            int col = colTile + wn + nt * 8 + 2 * t;
            #pragma unroll
            for (int dr = 0; dr < 2; dr++) {
                int r = rowTile + wm + mt * 16 + g + dr * 8;
                float v0 = c[mt][nt][dr * 2 + 0] + bias[col];
                float v1 = c[mt][nt][dr * 2 + 1] + bias[col + 1];
                if (z < 2) {
                    v0 = 0.5f * v0 * (1.0f + erff(v0 * 0.70710678118654752440f));
                    v1 = 0.5f * v1 * (1.0f + erff(v1 * 0.70710678118654752440f));
                }
                *(float2*)&C[(long)r * Dd + col] = make_float2(v0, v1);
            }
        }
}

// ------------------------- fused head GEMMs + phasor (z=2, 64x64 tile) -------
// 256 threads, 8 warps of 16x32: wm=(wid&3)*16, wn=(wid>>2)*32.
__global__ void phasor_gemm_kernel(const float* __restrict__ x,
                                   const float* __restrict__ pos_k, const float* __restrict__ pos_q,
                                   const float* __restrict__ hk,   const float* __restrict__ hq,
                                   const float* __restrict__ w2_k, const float* __restrict__ b2_k,
                                   const float* __restrict__ wa_k, const float* __restrict__ ba_k,
                                   const float* __restrict__ w2_q, const float* __restrict__ b2_q,
                                   const float* __restrict__ wa_q, const float* __restrict__ ba_q,
                                   float* __restrict__ kk, float* __restrict__ qq)
{
    const int z = blockIdx.z;
    const float* h   = z ? hq    : hk;
    const float* pos = z ? pos_q : pos_k;
    const float* W2  = z ? w2_q  : w2_k;
    const float* B2  = z ? b2_q  : b2_k;
    const float* Wa  = z ? wa_q  : wa_k;
    const float* Ba  = z ? ba_q  : ba_k;
    float* out       = z ? qq    : kk;

    __shared__ __align__(16) float Ah[2][16 * 68];
    __shared__ __align__(16) float Ax[2][16 * 68];
    __shared__ __align__(16) float Bp[2][16 * 68];
    __shared__ __align__(16) float Bm[2][16 * 68];

    const int tid  = threadIdx.x;
    const int lane = tid & 31, wid = tid >> 5;
    const int wm = (wid & 3) * 16, wn = (wid >> 2) * 32;
    const int g = lane >> 2, t = lane & 3;
    const int rowTile = blockIdx.y * 64;

    float cP[1][4][4] = {};
    float cA[1][4][4] = {};

    // A loads: m=tid>>2 (0..63), kq=(tid&3)*4 -> one float4 each
    const int am = tid >> 2, akq = (tid & 3) * 4;
    const int arow = rowTile + am;
    const int prow = arow & (Ll - 1);
    float4 vh, vx, vp; P4 p2, pm;

    auto LDG = [&](int k0) {
        vh = *(const float4*)&h[(long)arow * Dd + k0 + akq];
        vx = *(const float4*)&x[(long)arow * Dd + k0 + akq];
        vp = *(const float4*)&pos[(long)prow * Dd + k0 + akq];
        ldgB_kn(p2, W2, Kk, 0, k0, tid);
        ldgB_kn(pm, Wa, Kk, 0, k0, tid);
    };
    auto STS = [&](int nb) {
        Ah[nb][(akq + 0) * 68 + am] = to_tf32(vh.x);
        Ah[nb][(akq + 1) * 68 + am] = to_tf32(vh.y);
        Ah[nb][(akq + 2) * 68 + am] = to_tf32(vh.z);
        Ah[nb][(akq + 3) * 68 + am] = to_tf32(vh.w);
        Ax[nb][(akq + 0) * 68 + am] = to_tf32(vx.x + vp.x);
        Ax[nb][(akq + 1) * 68 + am] = to_tf32(vx.y + vp.y);
        Ax[nb][(akq + 2) * 68 + am] = to_tf32(vx.z + vp.z);
        Ax[nb][(akq + 3) * 68 + am] = to_tf32(vx.w + vp.w);
        stsB_kn(Bp[nb], p2, tid);
        stsB_kn(Bm[nb], pm, tid);
    };

    LDG(0); STS(0);
    __syncthreads();

    const int T = Dd >> 4;
    for (int ti = 0; ti < T; ti++) {
        if (ti + 1 < T) LDG((ti + 1) << 4);
        mma_frag<1, 68, 68>(Ah[ti & 1], Bp[ti & 1], wm, wn, g, t, cP);
        mma_frag<1, 68, 68>(Ax[ti & 1], Bm[ti & 1], wm, wn, g, t, cA);
        if (ti + 1 < T) { STS((ti + 1) & 1); __syncthreads(); }
    }

    #pragma unroll
    for (int nt = 0; nt < 4; nt++) {
        int col = wn + nt * 8 + 2 * t;
        #pragma unroll
        for (int dr = 0; dr < 2; dr++) {
            int n = rowTile + wm + g + dr * 8;
            #pragma unroll
            for (int dc = 0; dc < 2; dc++) {
                int cc = col + dc;
                float p = cP[0][nt][dr * 2 + dc] + B2[cc];
                float a = cA[0][nt][dr * 2 + dc] + Ba[cc];
                float ph = tanhf(p) * PIv;
                float sp = fmaxf(a, 0.0f) + log1pf(expf(-fabsf(a)));
                float amp = sp + 0.1f;
                float s, cs;
                sincosf(ph, &s, &cs);
                out[(long)n * K2 + cc]      = amp * cs;
                out[(long)n * K2 + Kk + cc] = amp * s;
            }
        }
    }
}

// ------------------------- fused retrieval GEMM: ret = A@V + QQ@S ------------
// 128x64 tile; 16 logical ktiles: ti<8 -> (A,V), ti>=8 -> (QQ,S).
__global__ void ret_gemm_kernel(const float* __restrict__ Amat, const float* __restrict__ Vm,
                                const float* __restrict__ QQ,   const float* __restrict__ S,
                                float* __restrict__ ret)
{
    const int z = blockIdx.z;
    const float* Ab = Amat + (long)z * CH * CH;
    const float* Vb = Vm   + (long)z * CH * Dd;
    const float* Qb = QQ   + (long)z * CH * K2;
    const float* Sb = S    + (long)z * K2 * Dd;
    float*       Cb = ret  + (long)z * CH * Dd;

    __shared__ __align__(16) float As[2][16 * 132];
    __shared__ __align__(16) float Bs[2][16 * 68];

    const int tid  = threadIdx.x;
    const int lane = tid & 31, wid = tid >> 5;
    const int wm = (wid & 3) * 32, wn = (wid >> 2) * 32;
    const int g = lane >> 2, t = lane & 3;
    const int colTile = blockIdx.x * 64;

    float c[2][4][4] = {};
    P8 pa; P4 pb;

    auto LDG = [&](int ti) {
        const float* Ap = (ti < 8) ? Ab : Qb;
        const float* Bp = (ti < 8) ? Vb : Sb;
        int k0 = (ti & 7) << 4;
        ldgA_mk(pa, Ap, 128, 0, k0, tid);
        ldgB_kn(pb, Bp, Dd, colTile, k0, tid);
    };

    LDG(0);
    stsA_mk(As[0], pa, tid); stsB_kn(Bs[0], pb, tid);
    __syncthreads();

    for (int ti = 0; ti < 16; ti++) {
        if (ti + 1 < 16) LDG(ti + 1);
        mma_frag<2, 132, 68>(As[ti & 1], Bs[ti & 1], wm, wn, g, t, c);
        if (ti + 1 < 16) {
            int nb = (ti + 1) & 1;
            stsA_mk(As[nb], pa, tid); stsB_kn(Bs[nb], pb, tid);
            __syncthreads();
        }
    }

    #pragma unroll
    for (int mt = 0; mt < 2; mt++)
        #pragma unroll
        for (int nt = 0; nt < 4; nt++) {
            int col = colTile + wn + nt * 8 + 2 * t;
            #pragma unroll
            for (int dr = 0; dr < 2; dr++) {
                int r = wm + mt * 16 + g + dr * 8;
                *(float2*)&Cb[(long)r * Dd + col] =
                    make_float2(c[mt][nt][dr * 2 + 0], c[mt][nt][dr * 2 + 1]);
            }
        }
}

// ------------------------- small kernels ------------------------------------
// exclusive prefix: one thread per (b, chunk, float4-element), redundant sums.
__global__ void prefix_kernel()
{
    const int KD4 = K2 * Dd / 4;   // 8192
    int idx = blockIdx.x * blockDim.x + threadIdx.x;
    if (idx >= Bb * NC * KD4) return;
    int r  = idx % KD4;
    int bc = idx / KD4;
    int cc = bc % NC;
    int b  = bc / NC;
    const float4* G4 = reinterpret_cast<const float4*>(g_G);
    float4*       S4 = reinterpret_cast<float4*>(g_S);
    float4 acc = make_float4(0.f, 0.f, 0.f, 0.f);
    for (int cp = 0; cp < cc; cp++) {
        float4 gv = G4[(long)(b * NC + cp) * KD4 + r];
        acc.x += gv.x; acc.y += gv.y; acc.z += gv.z; acc.w += gv.w;
    }
    S4[idx] = acc;
}

// normalize by sqrt((l+1)*K), layernorm
__global__ void ln_kernel(const float* __restrict__ ret,
                          const float* __restrict__ gg,
                          const float* __restrict__ bb,
                          float* __restrict__ rn)
{
    int n = blockIdx.x;
    int l = n % Ll;
    int d = threadIdx.x;      // 256 threads == D
    float v = ret[(long)n * Dd + d] * rsqrtf((float)(l + 1) * (float)Kk);

    float s = v, s2 = v * v;
    #pragma unroll
    for (int o = 16; o; o >>= 1) {
        s  += __shfl_xor_sync(0xffffffffu, s,  o);
        s2 += __shfl_xor_sync(0xffffffffu, s2, o);
    }
    __shared__ float ss[8], ss2[8];
    int w = d >> 5, lane = d & 31;
    if (lane == 0) { ss[w] = s; ss2[w] = s2; }
    __syncthreads();
    if (w == 0) {
        float a  = (lane < 8) ? ss[lane]  : 0.0f;
        float a2 = (lane < 8) ? ss2[lane] : 0.0f;
        #pragma unroll
        for (int o = 4; o; o >>= 1) {
            a  += __shfl_xor_sync(0xffffffffu, a,  o);
            a2 += __shfl_xor_sync(0xffffffffu, a2, o);
        }
        if (lane == 0) { ss[0] = a; ss2[0] = a2; }
    }
    __syncthreads();
    float mu  = ss[0] / Dd;
    float var = ss2[0] / Dd - mu * mu;
    rn[(long)n * Dd + d] = (v - mu) * rsqrtf(var + EPSv) * gg[d] + bb[d];
}

// ------------------------- host launcher ------------------------------------
extern "C" void kernel_launch(void* const* d_in, const int* in_sizes, int n_in,
                              void* d_out, int out_size)
{
    const float* x     = (const float*)d_in[0];
    const float* pos_k = (const float*)d_in[1];
    const float* w1_k  = (const float*)d_in[2];
    const float* b1_k  = (const float*)d_in[3];
    const float* w2_k  = (const float*)d_in[4];
    const float* b2_k  = (const float*)d_in[5];
    const float* wa_k  = (const float*)d_in[6];
    const float* ba_k  = (const float*)d_in[7];
    const float* pos_q = (const float*)d_in[8];
    const float* w1_q  = (const float*)d_in[9];
    const float* b1_q  = (const float*)d_in[10];
    const float* w2_q  = (const float*)d_in[11];
    const float* b2_q  = (const float*)d_in[12];
    const float* wa_q  = (const float*)d_in[13];
    const float* ba_q  = (const float*)d_in[14];
    const float* wv    = (const float*)d_in[15];
    const float* bv    = (const float*)d_in[16];
    const float* ln_g  = (const float*)d_in[17];
    const float* ln_b  = (const float*)d_in[18];
    const float* wo    = (const float*)d_in[19];
    const float* bo    = (const float*)d_in[20];
    float* out = (float*)d_out;

    float *hk, *hq, *kk, *qq, *V, *G, *S, *Amat, *ret, *rn;
    cudaGetSymbolAddress((void**)&hk,   g_hk);
    cudaGetSymbolAddress((void**)&hq,   g_hq);
    cudaGetSymbolAddress((void**)&kk,   g_kk);
    cudaGetSymbolAddress((void**)&qq,   g_qq);
    cudaGetSymbolAddress((void**)&V,    g_V);
    cudaGetSymbolAddress((void**)&G,    g_G);
    cudaGetSymbolAddress((void**)&S,    g_S);
    cudaGetSymbolAddress((void**)&Amat, g_A);
    cudaGetSymbolAddress((void**)&ret,  g_ret);
    cudaGetSymbolAddress((void**)&rn,   g_rn);

    // 1. hk = gelu((x+pos_k)@w1_k+b1), hq likewise, V = x@wv+bv
    enc_gemm_kernel<<<dim3(4, 16, 3), 256>>>(x, pos_k, pos_q,
                                             w1_k, b1_k, w1_q, b1_q, wv, bv,
                                             hk, hq, V);

    // 2. fused head GEMMs + phasor -> kk, qq
    phasor_gemm_kernel<<<dim3(1, 32, 2), 256>>>(x, pos_k, pos_q, hk, hq,
                                                w2_k, b2_k, wa_k, ba_k,
                                                w2_q, b2_q, wa_q, ba_q,
                                                kk, qq);

    // 3. per-chunk state: G[c] = KK_c^T @ V_c
    tgemm_kernel<M_PLAIN, true, false><<<dim3(4, 1, NCH), 256>>>(
        kk, V, nullptr, nullptr, G, K2, Dd, CH,
        (long)CH * K2, (long)CH * Dd, (long)K2 * Dd);

    // 4. exclusive prefix over chunks -> S (redundant-parallel)
    prefix_kernel<<<(Bb * NC * (K2 * Dd / 4) + 255) / 256, 256>>>();

    // 5. intra-chunk attention matrix A = tril(QQ_c @ KK_c^T)
    tgemm_kernel<M_MASK, false, true><<<dim3(2, 1, NCH), 256>>>(
        qq, kk, nullptr, nullptr, Amat, CH, CH, K2,
        (long)CH * K2, (long)CH * K2, (long)CH * CH);

    // 6. ret_c = A_c @ V_c + QQ_c @ S_c
    ret_gemm_kernel<<<dim3(4, 1, NCH), 256>>>(Amat, V, qq, S, ret);

    // 7. normalize + layernorm
    ln_kernel<<<NTOK, 256>>>(ret, ln_g, ln_b, rn);

    // 8. out = x + rn @ wo + bo
    tgemm_kernel<M_RESID, false, false><<<dim3(4, 16, 1), 256>>>(
        rn, wo, bo, x, out, NTOK, Dd, Dd, 0, 0, 0);
}